// round 16
// baseline (speedup 1.0000x reference)
#include <cuda_runtime.h>
#include <cuda_fp16.h>

#define NB    8
#define CIN   256
#define CI    128
#define NPIX  2304          // 48*48
#define TN    128           // attn n tile per CTA
#define TM    64            // attn m tile
#define NNT   (NPIX/TN)     // 18
#define NMT   (NPIX/TM)     // 36

#define QSTR  136           // halves stride, 128-col tiles (272B rows)
#define VSTR  72            // halves stride, 64-col tiles (144B rows)

// attn smem (halves): Q + double-buffered K + V + S
#define QH_H  0
#define QL_H  (128*QSTR)
#define KB_H  (2*128*QSTR)
#define KBUF  (2*64*QSTR)
#define KH_OF(buf) (KB_H + (buf)*KBUF)
#define KL_OF(buf) (KH_OF(buf) + 64*QSTR)
#define VH_H  (KB_H + 2*KBUF)
#define VL_H  (VH_H + 128*VSTR)
#define SH_H  (VL_H + 128*VSTR)
#define SL_H  (SH_H + 128*VSTR)
#define ATTN_SMEM_H (SL_H + 128*VSTR)      // 106496 halves = 212992 B

// conv smem (halves): resident xT hi/lo + double-buffered w chunks
#define XSTR  264           // halves stride, 256-col xT rows (528B = 132w = 4 mod 32: proven class)
#define WSTR  72
#define BSTR  131           // f32 bounce stride (2-way read conflicts only)
#define XH_F2 0
#define XL_F2 (128*XSTR)                    // 33792
#define WBASE (2*128*XSTR)                  // 67584
#define WBUF_SZ (2*128*WSTR)                // 18432 halves per buf (hi+lo)
#define WH_OF(buf) (WBASE + (buf)*WBUF_SZ)
#define WL_OF(buf) (WH_OF(buf) + 128*WSTR)
#define CONV_SMEM_H (WBASE + 2*WBUF_SZ)     // 104448 halves = 208896 B

// ---------------- cp.async ----------------
__device__ __forceinline__ unsigned s2u(const void* p) {
    unsigned a;
    asm("{ .reg .u64 t; cvta.to.shared.u64 t, %1; cvt.u32.u64 %0, t; }"
        : "=r"(a) : "l"(p));
    return a;
}
__device__ __forceinline__ void cp16(unsigned dst, const void* src) {
    asm volatile("cp.async.cg.shared.global [%0], [%1], 16;" :: "r"(dst), "l"(src));
}
__device__ __forceinline__ void cp_commit() { asm volatile("cp.async.commit_group;"); }
__device__ __forceinline__ void cp_wait0()  { asm volatile("cp.async.wait_group 0;" ::: "memory"); }
__device__ __forceinline__ void cp_wait1()  { asm volatile("cp.async.wait_group 1;" ::: "memory"); }
__device__ __forceinline__ void cp_wait2()  { asm volatile("cp.async.wait_group 2;" ::: "memory"); }

// ---------------- mma.sync + ldmatrix (mappings verified R13/R14) ----------------
__device__ __forceinline__ void ldm4(unsigned* r, unsigned addr) {
    asm volatile("ldmatrix.sync.aligned.m8n8.x4.shared.b16 {%0,%1,%2,%3}, [%4];"
        : "=r"(r[0]), "=r"(r[1]), "=r"(r[2]), "=r"(r[3]) : "r"(addr));
}
__device__ __forceinline__ void ldmA(unsigned* r, unsigned base, int offh,
                                     int r0, int c0, int stride, int lane) {
    int g = lane >> 3, rr = lane & 7;
    int row = r0 + rr + ((g & 1) << 3);
    int col = c0 + ((g >> 1) << 3);
    ldm4(r, base + (unsigned)(offh + row * stride + col) * 2);
}
__device__ __forceinline__ void ldmB(unsigned* r, unsigned base, int offh,
                                     int r0, int c0, int stride, int lane) {
    int g = lane >> 3, rr = lane & 7;
    int row = r0 + rr + ((g >> 1) << 3);
    int col = c0 + ((g & 1) << 3);
    ldm4(r, base + (unsigned)(offh + row * stride + col) * 2);
}
__device__ __forceinline__ void mma16816(float* c, const unsigned* a, const unsigned* b) {
    asm volatile("mma.sync.aligned.m16n8k16.row.col.f32.f16.f16.f32 "
        "{%0,%1,%2,%3}, {%4,%5,%6,%7}, {%8,%9}, {%0,%1,%2,%3};"
        : "+f"(c[0]), "+f"(c[1]), "+f"(c[2]), "+f"(c[3])
        : "r"(a[0]), "r"(a[1]), "r"(a[2]), "r"(a[3]), "r"(b[0]), "r"(b[1]));
}

// ---------------- scratch (indexed by attn dir-of-use) ----------------
__device__ __half g_Qh[2][NB][NPIX][CI];   // [pix n][c]
__device__ __half g_Ql[2][NB][NPIX][CI];
__device__ __half g_Kh[2][NB][NPIX][CI];   // [pix m][c]
__device__ __half g_Kl[2][NB][NPIX][CI];
__device__ __half g_Vh[2][NB][CI][NPIX];   // [c][pix m]
__device__ __half g_Vl[2][NB][CI][NPIX];
__device__ __half g_wh[6][CI][CIN];        // w [o][c], hi/lo
__device__ __half g_wl[6][CI][CIN];

// ---------------- w split ----------------
__global__ void wsplit_kernel(const float* __restrict__ w0, const float* __restrict__ w1,
                              const float* __restrict__ w2, const float* __restrict__ w3,
                              const float* __restrict__ w4, const float* __restrict__ w5)
{
    int conv = blockIdx.x;
    const float* w;
    switch (conv) {
        case 0: w = w0; break; case 1: w = w1; break; case 2: w = w2; break;
        case 3: w = w3; break; case 4: w = w4; break; default: w = w5; break;
    }
    for (int idx = threadIdx.x; idx < CI * CIN; idx += blockDim.x) {
        float v = w[idx];
        __half h = __float2half_rn(v);
        g_wh[conv][0][idx] = h;
        g_wl[conv][0][idx] = __float2half_rn(v - __half2float(h));
    }
}

// ---------------- w chunk prefetch ----------------
__device__ __forceinline__ void prefetch_w(unsigned base, int buf, int conv, int cc, int t)
{
    const __half* wh = &g_wh[conv][0][0];
    const __half* wl = &g_wl[conv][0][0];
    #pragma unroll
    for (int i = 0; i < 4; i++) {
        int idx = t + i * 256;
        int r = idx >> 3, u = idx & 7;
        cp16(base + (unsigned)(WH_OF(buf) + r * WSTR + u * 8) * 2,
             wh + (size_t)r * CIN + cc * 64 + u * 8);
        cp16(base + (unsigned)(WL_OF(buf) + r * WSTR + u * 8) * 2,
             wl + (size_t)r * CIN + cc * 64 + u * 8);
    }
    cp_commit();
}

// ---------------- fused conv: all 3 convs of one x tile on tensor cores ----------------
// grid: (NPIX/128, NB, 2 which), 256 threads
// QK-mode: C[pix][o] (A=xT, B=w); V-mode: C[o][pix] (A=w, B=xT)
__global__ __launch_bounds__(256, 1) void conv_fused_kernel(
    const float* __restrict__ x1, const float* __restrict__ x2,
    const float* __restrict__ bv1, const float* __restrict__ bk1, const float* __restrict__ bq1,
    const float* __restrict__ bv2, const float* __restrict__ bk2, const float* __restrict__ bq2)
{
    extern __shared__ __half smc[];
    const unsigned base = s2u(smc);
    const int t = threadIdx.x, lane = t & 31, wid = t >> 5;

    const int gp0   = blockIdx.x * 128;
    const int b     = blockIdx.y;
    const int which = blockIdx.z;
    const int cbase = which * 3;

    const float* x = (which ? x2 : x1) + (size_t)b * CIN * NPIX;

    // prefetch w step 0 (conv v, chunk 0) into buf 0 — overlaps phase 0
    prefetch_w(base, 0, cbase, 0, t);

    // ---- phase 0: stage xT fp16 hi/lo [128 pix][256 c] via f32 bounce (aliases buf 1) ----
    {
        float* bounce = (float*)(smc + WH_OF(1));   // [64 c][BSTR] f32
        for (int cc = 0; cc < 4; cc++) {
            #pragma unroll
            for (int i = 0; i < 8; i++) {
                int idx = t + i * 256;                // 2048 float4
                int r = idx >> 5, q = idx & 31;
                float4 v = *(const float4*)&x[(size_t)(cc * 64 + r) * NPIX + gp0 + q * 4];
                bounce[r * BSTR + q * 4 + 0] = v.x;
                bounce[r * BSTR + q * 4 + 1] = v.y;
                bounce[r * BSTR + q * 4 + 2] = v.z;
                bounce[r * BSTR + q * 4 + 3] = v.w;
            }
            __syncthreads();
            #pragma unroll
            for (int j = 0; j < 16; j++) {
                int pix = wid * 16 + j;
                float v0 = bounce[(lane * 2)     * BSTR + pix];
                float v1 = bounce[(lane * 2 + 1) * BSTR + pix];
                __half h0 = __float2half_rn(v0);
                __half h1 = __float2half_rn(v1);
                __half l0 = __float2half_rn(v0 - __half2float(h0));
                __half l1 = __float2half_rn(v1 - __half2float(h1));
                int o = pix * XSTR + cc * 64 + lane * 2;
                *(half2*)(smc + XH_F2 + o) = __halves2half2(h0, h1);
                *(half2*)(smc + XL_F2 + o) = __halves2half2(l0, l1);
            }
            __syncthreads();
        }
    }

    const int m0w = (wid & 3) * 32;
    const int n0w = (wid >> 2) * 64;

    for (int ci = 0; ci < 3; ci++) {
        const int conv = cbase + ci;
        const bool vmode = (ci == 0);
        const float* bias;
        __half *oH, *oL;
        switch (conv) {
            case 0:  bias = bv1; oH = &g_Vh[1][b][0][0]; oL = &g_Vl[1][b][0][0]; break;
            case 1:  bias = bk1; oH = &g_Kh[1][b][0][0]; oL = &g_Kl[1][b][0][0]; break;
            case 2:  bias = bq1; oH = &g_Qh[0][b][0][0]; oL = &g_Ql[0][b][0][0]; break;
            case 3:  bias = bv2; oH = &g_Vh[0][b][0][0]; oL = &g_Vl[0][b][0][0]; break;
            case 4:  bias = bk2; oH = &g_Kh[0][b][0][0]; oL = &g_Kl[0][b][0][0]; break;
            default: bias = bq2; oH = &g_Qh[1][b][0][0]; oL = &g_Ql[1][b][0][0]; break;
        }

        float facc[2][8][4];
        if (!vmode) {
            #pragma unroll
            for (int n8 = 0; n8 < 8; n8++) {
                int o = n0w + n8 * 8 + (lane & 3) * 2;
                float b0 = bias[o], b1 = bias[o + 1];
                #pragma unroll
                for (int mf = 0; mf < 2; mf++) {
                    facc[mf][n8][0] = b0; facc[mf][n8][1] = b1;
                    facc[mf][n8][2] = b0; facc[mf][n8][3] = b1;
                }
            }
        } else {
            #pragma unroll
            for (int mf = 0; mf < 2; mf++) {
                int r = m0w + mf * 16 + (lane >> 2);
                float br = bias[r], br8 = bias[r + 8];
                #pragma unroll
                for (int n8 = 0; n8 < 8; n8++) {
                    facc[mf][n8][0] = br;  facc[mf][n8][1] = br;
                    facc[mf][n8][2] = br8; facc[mf][n8][3] = br8;
                }
            }
        }

        for (int cc = 0; cc < 4; cc++) {
            const int s = ci * 4 + cc;
            __syncthreads();                // all warps done with buf (s+1)&1 & prev compute
            if (s < 11)
                prefetch_w(base, (s + 1) & 1, cbase + (s + 1) / 4, (s + 1) & 3, t);
            if (s < 11) cp_wait1(); else cp_wait0();
            __syncthreads();                // buffer s&1 visible to all warps

            const int WHb = WH_OF(s & 1), WLb = WL_OF(s & 1);
            const int AH = vmode ? WHb : XH_F2;
            const int AL = vmode ? WLb : XL_F2;
            const int BH = vmode ? XH_F2 : WHb;
            const int BL = vmode ? XL_F2 : WLb;
            const int astr = vmode ? WSTR : XSTR;
            const int bstr = vmode ? XSTR : WSTR;
            const int acol = vmode ? 0 : cc * 64;
            const int bcol = vmode ? cc * 64 : 0;

            #pragma unroll
            for (int kk = 0; kk < 4; kk++) {
                const int k0 = kk * 16;
                unsigned aH[2][4], aL[2][4];
                ldmA(aH[0], base, AH, m0w,      acol + k0, astr, lane);
                ldmA(aH[1], base, AH, m0w + 16, acol + k0, astr, lane);
                ldmA(aL[0], base, AL, m0w,      acol + k0, astr, lane);
                ldmA(aL[1], base, AL, m0w + 16, acol + k0, astr, lane);
                #pragma unroll
                for (int nb = 0; nb < 4; nb++) {
                    unsigned bh[4], bl[4];
                    ldmB(bh, base, BH, n0w + nb * 16, bcol + k0, bstr, lane);
                    ldmB(bl, base, BL, n0w + nb * 16, bcol + k0, bstr, lane);
                    #pragma unroll
                    for (int mf = 0; mf < 2; mf++)
                        #pragma unroll
                        for (int jj = 0; jj < 2; jj++) {
                            float* c = facc[mf][nb * 2 + jj];
                            mma16816(c, aH[mf], bh + jj * 2);
                            mma16816(c, aH[mf], bl + jj * 2);
                            mma16816(c, aL[mf], bh + jj * 2);
                        }
                }
            }
        }

        // epilogue: hi/lo split writes (verified in R14)
        #pragma unroll
        for (int mf = 0; mf < 2; mf++)
            #pragma unroll
            for (int n8 = 0; n8 < 8; n8++) {
                float v0 = facc[mf][n8][0], v1 = facc[mf][n8][1];
                float v2 = facc[mf][n8][2], v3 = facc[mf][n8][3];
                __half h0 = __float2half_rn(v0), h1 = __float2half_rn(v1);
                __half h2 = __float2half_rn(v2), h3 = __float2half_rn(v3);
                __half l0 = __float2half_rn(v0 - __half2float(h0));
                __half l1 = __float2half_rn(v1 - __half2float(h1));
                __half l2 = __float2half_rn(v2 - __half2float(h2));
                __half l3 = __float2half_rn(v3 - __half2float(h3));
                if (!vmode) {
                    int r = m0w + mf * 16 + (lane >> 2);
                    int o = n0w + n8 * 8 + (lane & 3) * 2;
                    size_t p0 = (size_t)(gp0 + r) * CI + o;
                    size_t p1 = (size_t)(gp0 + r + 8) * CI + o;
                    *(half2*)&oH[p0] = __halves2half2(h0, h1);
                    *(half2*)&oL[p0] = __halves2half2(l0, l1);
                    *(half2*)&oH[p1] = __halves2half2(h2, h3);
                    *(half2*)&oL[p1] = __halves2half2(l2, l3);
                } else {
                    int o   = m0w + mf * 16 + (lane >> 2);
                    int pix = gp0 + n0w + n8 * 8 + (lane & 3) * 2;
                    size_t p0 = (size_t)o * NPIX + pix;
                    size_t p1 = (size_t)(o + 8) * NPIX + pix;
                    *(half2*)&oH[p0] = __halves2half2(h0, h1);
                    *(half2*)&oL[p0] = __halves2half2(l0, l1);
                    *(half2*)&oH[p1] = __halves2half2(h2, h3);
                    *(half2*)&oL[p1] = __halves2half2(l2, l3);
                }
            }
    }
}

// ---------------- copy x into first 256 channels of y ----------------
__global__ void copyx_kernel(const float* __restrict__ x1, const float* __restrict__ x2,
                             float* __restrict__ out)
{
    const size_t per = (size_t)NB * CIN * NPIX / 4;
    size_t idx4 = (size_t)blockIdx.x * blockDim.x + threadIdx.x;
    if (idx4 >= 2 * per) return;
    int which = idx4 >= per;
    size_t r  = idx4 - (size_t)which * per;
    size_t bb = r / ((size_t)CIN * NPIX / 4);
    size_t cn = r % ((size_t)CIN * NPIX / 4);
    const float4* src = (const float4*)(which ? x2 : x1);
    float4* dst = (float4*)out + (size_t)which * NB * 384 * NPIX / 4
                               + bb * (384 * NPIX / 4) + cn;
    *dst = src[r];
}

// ---------------- mma.sync fp16 hi/lo attention (K double-buffered) — R15 proven ----------------
__global__ __launch_bounds__(512, 1) void attn_kernel(float* __restrict__ out)
{
    extern __shared__ __half smh[];
    const unsigned base = s2u(smh);
    const int t    = threadIdx.x;
    const int lane = t & 31;
    const int wid  = t >> 5;

    const int gn0 = blockIdx.x * TN;
    const int b   = blockIdx.y;
    const int dir = blockIdx.z;

    const __half* Qhg = &g_Qh[dir][b][0][0];
    const __half* Qlg = &g_Ql[dir][b][0][0];
    const __half* Khg = &g_Kh[dir][b][0][0];
    const __half* Klg = &g_Kl[dir][b][0][0];
    const __half* Vhg = &g_Vh[dir][b][0][0];
    const __half* Vlg = &g_Vl[dir][b][0][0];

    const int wlo = wid & 7, whi = wid >> 3;
    const int n0q = wlo * 16, m0w = whi * 32;    // QK warp tile
    const int c0w = wlo * 16, n0w = whi * 64;    // PV warp tile

    #pragma unroll
    for (int i = 0; i < 8; i++) {
        int j = t + (i & 3) * 512;
        int r = j >> 4, ch = j & 15;
        if (i < 4)
            *(uint4*)(smh + QH_H + r * QSTR + ch * 8) =
                *(const uint4*)(Qhg + (size_t)(gn0 + r) * CI + ch * 8);
        else
            *(uint4*)(smh + QL_H + r * QSTR + ch * 8) =
                *(const uint4*)(Qlg + (size_t)(gn0 + r) * CI + ch * 8);
    }

    #pragma unroll
    for (int i = 0; i < 2; i++) {
        int j = t + i * 512;
        int r = j >> 4, ch = j & 15;
        cp16(base + (unsigned)(KH_OF(0) + r * QSTR + ch * 8) * 2,
             Khg + (size_t)r * CI + ch * 8);
        cp16(base + (unsigned)(KL_OF(0) + r * QSTR + ch * 8) * 2,
             Klg + (size_t)r * CI + ch * 8);
    }
    cp_commit();

    float facc[8][4];
    #pragma unroll
    for (int j = 0; j < 8; j++)
        #pragma unroll
        for (int p = 0; p < 4; p++) facc[j][p] = 0.f;

    for (int mt = 0; mt < NMT; mt++) {
        const int gm0 = mt * TM;
        __syncthreads();

        #pragma unroll
        for (int i = 0; i < 2; i++) {
            int j = t + i * 512;
            int r = j >> 3, ch = j & 7;
            cp16(base + (unsigned)(VH_H + r * VSTR + ch * 8) * 2,
                 Vhg + (size_t)r * NPIX + gm0 + ch * 8);
            cp16(base + (unsigned)(VL_H + r * VSTR + ch * 8) * 2,
                 Vlg + (size_t)r * NPIX + gm0 + ch * 8);
        }
        cp_commit();
        if (mt + 1 < NMT) {
            const int kb = (mt + 1) & 1;
            const int gk = gm0 + TM;
            #pragma unroll
            for (int i = 0; i < 2; i++) {
                int j = t + i * 512;
                int r = j >> 4, ch = j & 15;
                cp16(base + (unsigned)(KH_OF(kb) + r * QSTR + ch * 8) * 2,
                     Khg + (size_t)(gk + r) * CI + ch * 8);
                cp16(base + (unsigned)(KL_OF(kb) + r * QSTR + ch * 8) * 2,
                     Klg + (size_t)(gk + r) * CI + ch * 8);
            }
            cp_commit();
            cp_wait2();
        } else {
            cp_wait1();
        }
        __syncthreads();

        const int KHb = KH_OF(mt & 1), KLb = KL_OF(mt & 1);
        float sacc[4][4];
        #pragma unroll
        for (int j = 0; j < 4; j++)
            #pragma unroll
            for (int p = 0; p < 4; p++) sacc[j][p] = 0.f;

        #pragma unroll
        for (int kk = 0; kk < 8; kk++) {
            const int c0 = kk * 16;
            unsigned aH[4], aL[4];
            ldmA(aH, base, QH_H, n0q, c0, QSTR, lane);
            ldmA(aL, base, QL_H, n0q, c0, QSTR, lane);
            unsigned bH0[4], bH1[4], bL0[4], bL1[4];
            ldmB(bH0, base, KHb, m0w,      c0, QSTR, lane);
            ldmB(bH1, base, KHb, m0w + 16, c0, QSTR, lane);
            ldmB(bL0, base, KLb, m0w,      c0, QSTR, lane);
            ldmB(bL1, base, KLb, m0w + 16, c0, QSTR, lane);
            #pragma unroll
            for (int j = 0; j < 4; j++) {
                const unsigned* bh = ((j < 2) ? bH0 : bH1) + (j & 1) * 2;
                const unsigned* bl = ((j < 2) ? bL0 : bL1) + (j & 1) * 2;
                mma16816(sacc[j], aH, bh);
                mma16816(sacc[j], aH, bl);
                mma16816(sacc[j], aL, bh);
            }
        }

        #pragma unroll
        for (int j = 0; j < 4; j++) {
            const int m   = m0w + j * 8 + (lane & 3) * 2;
            const int nb0 = n0q + (lane >> 2);
            #pragma unroll
            for (int h = 0; h < 2; h++) {
                const int n = nb0 + h * 8;
                float s0 = __fdividef(1.f, 1.f + __expf(-sacc[j][h * 2]));
                float s1 = __fdividef(1.f, 1.f + __expf(-sacc[j][h * 2 + 1]));
                __half h0 = __float2half_rn(s0), h1 = __float2half_rn(s1);
                __half l0 = __float2half_rn(s0 - __half2float(h0));
                __half l1 = __float2half_rn(s1 - __half2float(h1));
                *(half2*)(smh + SH_H + n * VSTR + m) = __halves2half2(h0, h1);
                *(half2*)(smh + SL_H + n * VSTR + m) = __halves2half2(l0, l1);
            }
        }
        if (mt + 1 < NMT) cp_wait1();
        else              cp_wait0();
        __syncthreads();

        #pragma unroll
        for (int kk = 0; kk < 4; kk++) {
            const int mk = kk * 16;
            unsigned aVH[4], aVL[4];
            ldmA(aVH, base, VH_H, c0w, mk, VSTR, lane);
            ldmA(aVL, base, VL_H, c0w, mk, VSTR, lane);
            #pragma unroll
            for (int q = 0; q < 4; q++) {
                unsigned bSH[4], bSL[4];
                ldmB(bSH, base, SH_H, n0w + q * 16, mk, VSTR, lane);
                ldmB(bSL, base, SL_H, n0w + q * 16, mk, VSTR, lane);
                #pragma unroll
                for (int jj = 0; jj < 2; jj++) {
                    const int j = q * 2 + jj;
                    const unsigned* bh = bSH + jj * 2;
                    const unsigned* bl = bSL + jj * 2;
                    mma16816(facc[j], aVH, bh);
                    mma16816(facc[j], aVH, bl);
                    mma16816(facc[j], aVL, bh);
                }
            }
        }
    }

    float* ob = out + (size_t)dir * NB * 384 * NPIX
                    + (size_t)b * 384 * NPIX + (size_t)256 * NPIX;
    #pragma unroll
    for (int j = 0; j < 8; j++) {
        const int n = n0w + j * 8 + (lane & 3) * 2;
        const int c = c0w + (lane >> 2);
        *(float2*)&ob[(size_t)c * NPIX + gn0 + n] =
            make_float2(facc[j][0], facc[j][1]);
        *(float2*)&ob[(size_t)(c + 8) * NPIX + gn0 + n] =
            make_float2(facc[j][2], facc[j][3]);
    }
}

// ---------------- launch ----------------
extern "C" void kernel_launch(void* const* d_in, const int* in_sizes, int n_in,
                              void* d_out, int out_size)
{
    const float* x1  = (const float*)d_in[0];
    const float* x2  = (const float*)d_in[1];
    const float* wv1 = (const float*)d_in[2];  const float* bv1 = (const float*)d_in[3];
    const float* wk1 = (const float*)d_in[4];  const float* bk1 = (const float*)d_in[5];
    const float* wq1 = (const float*)d_in[6];  const float* bq1 = (const float*)d_in[7];
    const float* wv2 = (const float*)d_in[8];  const float* bv2 = (const float*)d_in[9];
    const float* wk2 = (const float*)d_in[10]; const float* bk2 = (const float*)d_in[11];
    const float* wq2 = (const float*)d_in[12]; const float* bq2 = (const float*)d_in[13];
    float* out = (float*)d_out;

    wsplit_kernel<<<6, 256>>>(wv1, wk1, wq1, wv2, wk2, wq2);

    {
        size_t smem = (size_t)CONV_SMEM_H * sizeof(__half);
        cudaFuncSetAttribute(conv_fused_kernel, cudaFuncAttributeMaxDynamicSharedMemorySize,
                             (int)smem);
        dim3 cg(NPIX / 128, NB, 2);
        conv_fused_kernel<<<cg, 256, smem>>>(x1, x2, bv1, bk1, bq1, bv2, bk2, bq2);
    }

    {
        size_t tot4 = 2ull * NB * CIN * NPIX / 4;
        int blocks = (int)((tot4 + 255) / 256);
        copyx_kernel<<<blocks, 256>>>(x1, x2, out);
    }

    {
        size_t smem = (size_t)ATTN_SMEM_H * sizeof(__half);
        cudaFuncSetAttribute(attn_kernel, cudaFuncAttributeMaxDynamicSharedMemorySize,
                             (int)smem);
        dim3 ag(NNT, NB, 2);
        attn_kernel<<<ag, 512, smem>>>(out);
    }
}

// round 17
// speedup vs baseline: 1.5418x; 1.5418x over previous
#include <cuda_runtime.h>
#include <cuda_fp16.h>

#define NB    8
#define CIN   256
#define CI    128
#define NPIX  2304          // 48*48
#define BN    64            // conv n tile
#define NT    (NPIX/BN)     // 36
#define TN    128           // attn n tile per CTA
#define TM    64            // attn m tile
#define NNT   (NPIX/TN)     // 18
#define NMT   (NPIX/TM)     // 36

#define QSTR  136           // halves stride, 128-col tiles (272B rows)
#define VSTR  72            // halves stride, 64-col tiles (144B rows)

// attn smem (halves): Q hi/lo + double-buffered K hi/lo + V (single) + S (single)
#define QH_H  0
#define QL_H  (128*QSTR)
#define KB_H  (2*128*QSTR)
#define KBUF  (2*64*QSTR)
#define KH_OF(buf) (KB_H + (buf)*KBUF)
#define KL_OF(buf) (KH_OF(buf) + 64*QSTR)
#define VH_H  (KB_H + 2*KBUF)
#define SH_H  (VH_H + 128*VSTR)
#define ATTN_SMEM_H (SH_H + 128*VSTR)      // 88064 halves = 176128 B

// ---------------- f32x2 packed helpers (conv) ----------------
__device__ __forceinline__ unsigned long long pack2(float lo, float hi) {
    unsigned long long d;
    asm("mov.b64 %0, {%1, %2};"
        : "=l"(d) : "r"(__float_as_uint(lo)), "r"(__float_as_uint(hi)));
    return d;
}
__device__ __forceinline__ unsigned long long fma2(unsigned long long a,
                                                   unsigned long long b,
                                                   unsigned long long c) {
    unsigned long long d;
    asm("fma.rn.f32x2 %0, %1, %2, %3;" : "=l"(d) : "l"(a), "l"(b), "l"(c));
    return d;
}
__device__ __forceinline__ float2 unpack2(unsigned long long v) {
    unsigned int lo, hi;
    asm("mov.b64 {%0, %1}, %2;" : "=r"(lo), "=r"(hi) : "l"(v));
    return make_float2(__uint_as_float(lo), __uint_as_float(hi));
}

// ---------------- cp.async ----------------
__device__ __forceinline__ unsigned s2u(const void* p) {
    unsigned a;
    asm("{ .reg .u64 t; cvta.to.shared.u64 t, %1; cvt.u32.u64 %0, t; }"
        : "=r"(a) : "l"(p));
    return a;
}
__device__ __forceinline__ void cp16(unsigned dst, const void* src) {
    asm volatile("cp.async.cg.shared.global [%0], [%1], 16;" :: "r"(dst), "l"(src));
}
__device__ __forceinline__ void cp_commit() { asm volatile("cp.async.commit_group;"); }
__device__ __forceinline__ void cp_wait0()  { asm volatile("cp.async.wait_group 0;" ::: "memory"); }
__device__ __forceinline__ void cp_wait1()  { asm volatile("cp.async.wait_group 1;" ::: "memory"); }
__device__ __forceinline__ void cp_wait2()  { asm volatile("cp.async.wait_group 2;" ::: "memory"); }

// ---------------- mma.sync + ldmatrix (mappings verified R13/R15) ----------------
__device__ __forceinline__ void ldm4(unsigned* r, unsigned addr) {
    asm volatile("ldmatrix.sync.aligned.m8n8.x4.shared.b16 {%0,%1,%2,%3}, [%4];"
        : "=r"(r[0]), "=r"(r[1]), "=r"(r[2]), "=r"(r[3]) : "r"(addr));
}
__device__ __forceinline__ void ldmA(unsigned* r, unsigned base, int offh,
                                     int r0, int c0, int stride, int lane) {
    int g = lane >> 3, rr = lane & 7;
    int row = r0 + rr + ((g & 1) << 3);
    int col = c0 + ((g >> 1) << 3);
    ldm4(r, base + (unsigned)(offh + row * stride + col) * 2);
}
__device__ __forceinline__ void ldmB(unsigned* r, unsigned base, int offh,
                                     int r0, int c0, int stride, int lane) {
    int g = lane >> 3, rr = lane & 7;
    int row = r0 + rr + ((g >> 1) << 3);
    int col = c0 + ((g & 1) << 3);
    ldm4(r, base + (unsigned)(offh + row * stride + col) * 2);
}
__device__ __forceinline__ void mma16816(float* c, const unsigned* a, const unsigned* b) {
    asm volatile("mma.sync.aligned.m16n8k16.row.col.f32.f16.f16.f32 "
        "{%0,%1,%2,%3}, {%4,%5,%6,%7}, {%8,%9}, {%0,%1,%2,%3};"
        : "+f"(c[0]), "+f"(c[1]), "+f"(c[2]), "+f"(c[3])
        : "r"(a[0]), "r"(a[1]), "r"(a[2]), "r"(a[3]), "r"(b[0]), "r"(b[1]));
}

// ---------------- scratch (indexed by attn dir-of-use) ----------------
__device__ __half g_Qh[2][NB][NPIX][CI];   // [pix n][c]
__device__ __half g_Ql[2][NB][NPIX][CI];
__device__ __half g_Kh[2][NB][NPIX][CI];   // [pix m][c]
__device__ __half g_Kl[2][NB][NPIX][CI];
__device__ __half g_Vh[2][NB][CI][NPIX];   // [c][pix m], single fp16
__device__ float  g_wT[6][CIN][CI];        // [c][o]

// ---------------- weight transpose ----------------
__global__ void wtrans_kernel(const float* __restrict__ w0, const float* __restrict__ w1,
                              const float* __restrict__ w2, const float* __restrict__ w3,
                              const float* __restrict__ w4, const float* __restrict__ w5)
{
    int conv = blockIdx.x;
    const float* w;
    switch (conv) {
        case 0: w = w0; break; case 1: w = w1; break; case 2: w = w2; break;
        case 3: w = w3; break; case 4: w = w4; break; default: w = w5; break;
    }
    for (int idx = threadIdx.x; idx < CI * CIN; idx += blockDim.x) {
        int o = idx / CIN;
        int c = idx % CIN;
        g_wT[conv][c][o] = w[o * CIN + c];
    }
}

// ---------------- 1x1 conv (fp32 math; fp16 hi/lo epilogue; V single fp16) ----------------
__global__ __launch_bounds__(256) void conv_kernel(
    const float* __restrict__ x1, const float* __restrict__ x2,
    const float* __restrict__ bv1, const float* __restrict__ bk1, const float* __restrict__ bq1,
    const float* __restrict__ bv2, const float* __restrict__ bk2, const float* __restrict__ bq2)
{
    const int conv = blockIdx.z;
    const int b    = blockIdx.y;
    const int gn0  = blockIdx.x * BN;

    const float* x = (conv < 3) ? x1 : x2;
    const float* bias;
    __half *oH = nullptr, *oL = nullptr;
    bool vmode = false;
    switch (conv) {
        case 0: bias = bv1; oH = &g_Vh[1][b][0][0]; vmode = true; break;
        case 3: bias = bv2; oH = &g_Vh[0][b][0][0]; vmode = true; break;
        case 1: bias = bk1; oH = &g_Kh[1][b][0][0]; oL = &g_Kl[1][b][0][0]; break;
        case 4: bias = bk2; oH = &g_Kh[0][b][0][0]; oL = &g_Kl[0][b][0][0]; break;
        case 2: bias = bq1; oH = &g_Qh[0][b][0][0]; oL = &g_Ql[0][b][0][0]; break;
        default: bias = bq2; oH = &g_Qh[1][b][0][0]; oL = &g_Ql[1][b][0][0]; break;
    }

    __shared__ float Ws[32][CI];
    __shared__ float Xs[32][BN];

    const int t  = threadIdx.x;
    const int tx = t & 15;
    const int ty = t >> 4;
    const int oA  = tx * 4;
    const int oB  = 64 + tx * 4;
    const int n0l = ty * 4;

    unsigned long long acc2[4][4];
    #pragma unroll
    for (int p = 0; p < 4; p++) {
        int ob0 = (p < 2) ? (oA + 2 * p) : (oB + 2 * (p - 2));
        unsigned long long bp = pack2(bias[ob0], bias[ob0 + 1]);
        #pragma unroll
        for (int j = 0; j < 4; j++) acc2[p][j] = bp;
    }

    const float* xb = x + (size_t)b * CIN * NPIX + gn0;
    const float* wt = &g_wT[conv][0][0];

    for (int c0 = 0; c0 < CIN; c0 += 32) {
        #pragma unroll
        for (int i = 0; i < 4; i++) {
            int idx4 = t + i * 256;
            int k = idx4 >> 5, o4 = idx4 & 31;
            *(float4*)&Ws[k][o4 * 4] = *(const float4*)&wt[(size_t)(c0 + k) * CI + o4 * 4];
        }
        #pragma unroll
        for (int i = 0; i < 2; i++) {
            int idx4 = t + i * 256;
            int k = idx4 >> 4, n4 = idx4 & 15;
            *(float4*)&Xs[k][n4 * 4] = *(const float4*)&xb[(size_t)(c0 + k) * NPIX + n4 * 4];
        }
        __syncthreads();
        #pragma unroll
        for (int k = 0; k < 32; k++) {
            float4 w0 = *(float4*)&Ws[k][oA];
            float4 w1 = *(float4*)&Ws[k][oB];
            float4 xv = *(float4*)&Xs[k][n0l];
            unsigned long long wp[4];
            wp[0] = pack2(w0.x, w0.y);  wp[1] = pack2(w0.z, w0.w);
            wp[2] = pack2(w1.x, w1.y);  wp[3] = pack2(w1.z, w1.w);
            float xr[4] = {xv.x, xv.y, xv.z, xv.w};
            #pragma unroll
            for (int j = 0; j < 4; j++) {
                unsigned long long xbcast = pack2(xr[j], xr[j]);
                #pragma unroll
                for (int p = 0; p < 4; p++)
                    acc2[p][j] = fma2(wp[p], xbcast, acc2[p][j]);
            }
        }
        __syncthreads();
    }

    float acc[8][4];
    #pragma unroll
    for (int p = 0; p < 4; p++)
        #pragma unroll
        for (int j = 0; j < 4; j++) {
            float2 v = unpack2(acc2[p][j]);
            acc[2 * p][j]     = v.x;   // 0-3 -> oA+0..3, 4-7 -> oB+0..3
            acc[2 * p + 1][j] = v.y;
        }

    if (!vmode) {
        #pragma unroll
        for (int j = 0; j < 4; j++) {
            size_t gn = gn0 + n0l + j;
            __half h[8], l[8];
            #pragma unroll
            for (int i = 0; i < 8; i++) {
                float v = acc[i][j];
                h[i] = __float2half_rn(v);
                l[i] = __float2half_rn(v - __half2float(h[i]));
            }
            *(half2*)&oH[gn * CI + oA]     = __halves2half2(h[0], h[1]);
            *(half2*)&oH[gn * CI + oA + 2] = __halves2half2(h[2], h[3]);
            *(half2*)&oH[gn * CI + oB]     = __halves2half2(h[4], h[5]);
            *(half2*)&oH[gn * CI + oB + 2] = __halves2half2(h[6], h[7]);
            *(half2*)&oL[gn * CI + oA]     = __halves2half2(l[0], l[1]);
            *(half2*)&oL[gn * CI + oA + 2] = __halves2half2(l[2], l[3]);
            *(half2*)&oL[gn * CI + oB]     = __halves2half2(l[4], l[5]);
            *(half2*)&oL[gn * CI + oB + 2] = __halves2half2(l[6], l[7]);
        }
    } else {
        // V: single fp16 (PV tolerance analysis: rounding errors sqrt-cancel over m)
        #pragma unroll
        for (int i = 0; i < 8; i++) {
            int c = (i < 4) ? (oA + i) : (oB + i - 4);
            __half h[4];
            #pragma unroll
            for (int j = 0; j < 4; j++) h[j] = __float2half_rn(acc[i][j]);
            size_t o = (size_t)c * NPIX + gn0 + n0l;
            *(half2*)&oH[o]     = __halves2half2(h[0], h[1]);
            *(half2*)&oH[o + 2] = __halves2half2(h[2], h[3]);
        }
    }
}

// ---------------- copy x into first 256 channels of y ----------------
__global__ void copyx_kernel(const float* __restrict__ x1, const float* __restrict__ x2,
                             float* __restrict__ out)
{
    const size_t per = (size_t)NB * CIN * NPIX / 4;
    size_t idx4 = (size_t)blockIdx.x * blockDim.x + threadIdx.x;
    if (idx4 >= 2 * per) return;
    int which = idx4 >= per;
    size_t r  = idx4 - (size_t)which * per;
    size_t bb = r / ((size_t)CIN * NPIX / 4);
    size_t cn = r % ((size_t)CIN * NPIX / 4);
    const float4* src = (const float4*)(which ? x2 : x1);
    float4* dst = (float4*)out + (size_t)which * NB * 384 * NPIX / 4
                               + bb * (384 * NPIX / 4) + cn;
    *dst = src[r];
}

// ---------------- attention: QK 3-term hi/lo, PV single-term fp16 ----------------
__global__ __launch_bounds__(512, 1) void attn_kernel(float* __restrict__ out)
{
    extern __shared__ __half smh[];
    const unsigned base = s2u(smh);
    const int t    = threadIdx.x;
    const int lane = t & 31;
    const int wid  = t >> 5;

    const int gn0 = blockIdx.x * TN;
    const int b   = blockIdx.y;
    const int dir = blockIdx.z;

    const __half* Qhg = &g_Qh[dir][b][0][0];
    const __half* Qlg = &g_Ql[dir][b][0][0];
    const __half* Khg = &g_Kh[dir][b][0][0];
    const __half* Klg = &g_Kl[dir][b][0][0];
    const __half* Vhg = &g_Vh[dir][b][0][0];

    const int wlo = wid & 7, whi = wid >> 3;
    const int n0q = wlo * 16, m0w = whi * 32;    // QK warp tile
    const int c0w = wlo * 16, n0w = whi * 64;    // PV warp tile

    // stage Q hi/lo [128][136]
    #pragma unroll
    for (int i = 0; i < 8; i++) {
        int j = t + (i & 3) * 512;
        int r = j >> 4, ch = j & 15;
        if (i < 4)
            *(uint4*)(smh + QH_H + r * QSTR + ch * 8) =
                *(const uint4*)(Qhg + (size_t)(gn0 + r) * CI + ch * 8);
        else
            *(uint4*)(smh + QL_H + r * QSTR + ch * 8) =
                *(const uint4*)(Qlg + (size_t)(gn0 + r) * CI + ch * 8);
    }

    // prefetch K(0) into buffer 0
    #pragma unroll
    for (int i = 0; i < 2; i++) {
        int j = t + i * 512;
        int r = j >> 4, ch = j & 15;
        cp16(base + (unsigned)(KH_OF(0) + r * QSTR + ch * 8) * 2,
             Khg + (size_t)r * CI + ch * 8);
        cp16(base + (unsigned)(KL_OF(0) + r * QSTR + ch * 8) * 2,
             Klg + (size_t)r * CI + ch * 8);
    }
    cp_commit();

    float facc[8][4];
    #pragma unroll
    for (int j = 0; j < 8; j++)
        #pragma unroll
        for (int p = 0; p < 4; p++) facc[j][p] = 0.f;

    for (int mt = 0; mt < NMT; mt++) {
        const int gm0 = mt * TM;
        __syncthreads();   // prev PV done reading S/V (and Q staged on iter 0)

        // V(mt) single fp16 [128 c][64 m]: 1024 cp16 over 512 threads
        #pragma unroll
        for (int i = 0; i < 2; i++) {
            int j = t + i * 512;
            int r = j >> 3, ch = j & 7;
            cp16(base + (unsigned)(VH_H + r * VSTR + ch * 8) * 2,
                 Vhg + (size_t)r * NPIX + gm0 + ch * 8);
        }
        cp_commit();
        // K(mt+1): hidden under sigmoid+PV
        if (mt + 1 < NMT) {
            const int kb = (mt + 1) & 1;
            const int gk = gm0 + TM;
            #pragma unroll
            for (int i = 0; i < 2; i++) {
                int j = t + i * 512;
                int r = j >> 4, ch = j & 15;
                cp16(base + (unsigned)(KH_OF(kb) + r * QSTR + ch * 8) * 2,
                     Khg + (size_t)(gk + r) * CI + ch * 8);
                cp16(base + (unsigned)(KL_OF(kb) + r * QSTR + ch * 8) * 2,
                     Klg + (size_t)(gk + r) * CI + ch * 8);
            }
            cp_commit();
            cp_wait2();    // K(mt) landed; V(mt), K(mt+1) in flight
        } else {
            cp_wait1();    // K(mt) landed; V(mt) in flight
        }
        __syncthreads();

        // ---- QK: S[16n x 32m] per warp; Qh.Kh + Qh.Kl + Ql.Kh ----
        const int KHb = KH_OF(mt & 1), KLb = KL_OF(mt & 1);
        float sacc[4][4];
        #pragma unroll
        for (int j = 0; j < 4; j++)
            #pragma unroll
            for (int p = 0; p < 4; p++) sacc[j][p] = 0.f;

        #pragma unroll
        for (int kk = 0; kk < 8; kk++) {
            const int c0 = kk * 16;
            unsigned aH[4], aL[4];
            ldmA(aH, base, QH_H, n0q, c0, QSTR, lane);
            ldmA(aL, base, QL_H, n0q, c0, QSTR, lane);
            unsigned bH0[4], bH1[4], bL0[4], bL1[4];
            ldmB(bH0, base, KHb, m0w,      c0, QSTR, lane);
            ldmB(bH1, base, KHb, m0w + 16, c0, QSTR, lane);
            ldmB(bL0, base, KLb, m0w,      c0, QSTR, lane);
            ldmB(bL1, base, KLb, m0w + 16, c0, QSTR, lane);
            #pragma unroll
            for (int j = 0; j < 4; j++) {
                const unsigned* bh = ((j < 2) ? bH0 : bH1) + (j & 1) * 2;
                const unsigned* bl = ((j < 2) ? bL0 : bL1) + (j & 1) * 2;
                mma16816(sacc[j], aH, bh);
                mma16816(sacc[j], aH, bl);
                mma16816(sacc[j], aL, bh);
            }
        }

        // ---- sigmoid -> S[n][m] single fp16 ----
        #pragma unroll
        for (int j = 0; j < 4; j++) {
            const int m   = m0w + j * 8 + (lane & 3) * 2;
            const int nb0 = n0q + (lane >> 2);
            #pragma unroll
            for (int h = 0; h < 2; h++) {
                const int n = nb0 + h * 8;
                float s0 = __fdividef(1.f, 1.f + __expf(-sacc[j][h * 2]));
                float s1 = __fdividef(1.f, 1.f + __expf(-sacc[j][h * 2 + 1]));
                *(half2*)(smh + SH_H + n * VSTR + m) =
                    __halves2half2(__float2half_rn(s0), __float2half_rn(s1));
            }
        }
        if (mt + 1 < NMT) cp_wait1();   // V(mt) landed; K(mt+1) still flying
        else              cp_wait0();
        __syncthreads();                // S + V visible

        // ---- PV: Fu[16c x 64n] per warp; single term Vh.Sh ----
        #pragma unroll
        for (int kk = 0; kk < 4; kk++) {
            const int mk = kk * 16;
            unsigned aVH[4];
            ldmA(aVH, base, VH_H, c0w, mk, VSTR, lane);
            #pragma unroll
            for (int q = 0; q < 4; q++) {
                unsigned bSH[4];
                ldmB(bSH, base, SH_H, n0w + q * 16, mk, VSTR, lane);
                #pragma unroll
                for (int jj = 0; jj < 2; jj++)
                    mma16816(facc[q * 2 + jj], aVH, bSH + jj * 2);
            }
        }
    }

    // ---- epilogue: Fu -> channels [256,384) of y ----
    float* ob = out + (size_t)dir * NB * 384 * NPIX
                    + (size_t)b * 384 * NPIX + (size_t)256 * NPIX;
    #pragma unroll
    for (int j = 0; j < 8; j++) {
        const int n = n0w + j * 8 + (lane & 3) * 2;
        const int c = c0w + (lane >> 2);
        *(float2*)&ob[(size_t)c * NPIX + gn0 + n] =
            make_float2(facc[j][0], facc[j][1]);
        *(float2*)&ob[(size_t)(c + 8) * NPIX + gn0 + n] =
            make_float2(facc[j][2], facc[j][3]);
    }
}

// ---------------- launch ----------------
extern "C" void kernel_launch(void* const* d_in, const int* in_sizes, int n_in,
                              void* d_out, int out_size)
{
    const float* x1  = (const float*)d_in[0];
    const float* x2  = (const float*)d_in[1];
    const float* wv1 = (const float*)d_in[2];  const float* bv1 = (const float*)d_in[3];
    const float* wk1 = (const float*)d_in[4];  const float* bk1 = (const float*)d_in[5];
    const float* wq1 = (const float*)d_in[6];  const float* bq1 = (const float*)d_in[7];
    const float* wv2 = (const float*)d_in[8];  const float* bv2 = (const float*)d_in[9];
    const float* wk2 = (const float*)d_in[10]; const float* bk2 = (const float*)d_in[11];
    const float* wq2 = (const float*)d_in[12]; const float* bq2 = (const float*)d_in[13];
    float* out = (float*)d_out;

    wtrans_kernel<<<6, 256>>>(wv1, wk1, wq1, wv2, wk2, wq2);

    dim3 cg(NT, NB, 6);
    conv_kernel<<<cg, 256>>>(x1, x2, bv1, bk1, bq1, bv2, bk2, bq2);

    {
        size_t tot4 = 2ull * NB * CIN * NPIX / 4;
        int blocks = (int)((tot4 + 255) / 256);
        copyx_kernel<<<blocks, 256>>>(x1, x2, out);
    }

    {
        size_t smem = (size_t)ATTN_SMEM_H * sizeof(__half);
        cudaFuncSetAttribute(attn_kernel, cudaFuncAttributeMaxDynamicSharedMemorySize,
                             (int)smem);
        dim3 ag(NNT, NB, 2);
        attn_kernel<<<ag, 512, smem>>>(out);
    }
}